// round 8
// baseline (speedup 1.0000x reference)
#include <cuda_runtime.h>
#include <math.h>

// Problem constants
#define PB 8
#define PN 1025
#define PD 1024
#define PH 16
#define PDh 64
#define PM (PB*PN)      // 8200 rows
#define PEPS 1e-8f

// Scratch (device globals: allocation-free rule)
__device__ unsigned g_hb  [(size_t)PM * 512];     // rmsnorm out, bf16 pairs
__device__ unsigned g_qkh [(size_t)PM * 1024];    // q|k bf16 pairs (q: 0..511, k: 512..1023)
__device__ float    g_v   [(size_t)PM * 1024];    // v fp32
__device__ unsigned g_yh  [(size_t)PM * 512];     // attention out, bf16 pairs
__device__ float    g_t1  [(size_t)PM * 1024];    // out proj, fp32
__device__ unsigned g_wqkv [3072 * 512];          // qkv_w bf16 pairs
__device__ unsigned g_wout [1024 * 512];
__device__ unsigned g_wgate[1024 * 512];

__device__ __forceinline__ float to_tf32(float x) {
    float r;
    asm("cvt.rna.tf32.f32 %0, %1;" : "=f"(r) : "f"(x));
    return r;
}
// pack two fp32 -> bf16x2 (lo = first arg)
__device__ __forceinline__ unsigned pack_bf2(float lo, float hi) {
    unsigned r;
    asm("cvt.rn.bf16x2.f32 %0, %1, %2;" : "=r"(r) : "f"(hi), "f"(lo));
    return r;
}
__device__ __forceinline__ float bf_lo(unsigned u) { return __uint_as_float(u << 16); }
__device__ __forceinline__ float bf_hi(unsigned u) { return __uint_as_float(u & 0xffff0000u); }

// cp.async helpers
__device__ __forceinline__ void cp_async16(void* smem_dst, const void* gmem_src, int src_bytes) {
    unsigned saddr = (unsigned)__cvta_generic_to_shared(smem_dst);
    asm volatile("cp.async.cg.shared.global [%0], [%1], 16, %2;\n"
                 :: "r"(saddr), "l"(gmem_src), "r"(src_bytes));
}
__device__ __forceinline__ void cp_commit() {
    asm volatile("cp.async.commit_group;\n" ::);
}
template<int N>
__device__ __forceinline__ void cp_wait() {
    asm volatile("cp.async.wait_group %0;\n" :: "n"(N));
}

#define MMA_BF16(c, a0,a1,a2,a3, b0,b1) \
    asm volatile("mma.sync.aligned.m16n8k16.row.col.f32.bf16.bf16.f32 " \
        "{%0,%1,%2,%3}, {%4,%5,%6,%7}, {%8,%9}, {%0,%1,%2,%3};" \
        : "+f"((c)[0]), "+f"((c)[1]), "+f"((c)[2]), "+f"((c)[3]) \
        : "r"(a0), "r"(a1), "r"(a2), "r"(a3), "r"(b0), "r"(b1))

#define MMA_TF32(c, a0,a1,a2,a3, b0,b1) \
    asm volatile("mma.sync.aligned.m16n8k8.row.col.f32.tf32.tf32.f32 " \
        "{%0,%1,%2,%3}, {%4,%5,%6,%7}, {%8,%9}, {%0,%1,%2,%3};" \
        : "+f"((c)[0]), "+f"((c)[1]), "+f"((c)[2]), "+f"((c)[3]) \
        : "r"(a0), "r"(a1), "r"(a2), "r"(a3), "r"(b0), "r"(b1))

// ---------------------------------------------------------------------------
// Kernel 0: fp32 -> bf16x2 weight conversion (n = element pairs)
// ---------------------------------------------------------------------------
__global__ __launch_bounds__(256) void cvt_bf16_kernel(
    const float* __restrict__ src, unsigned* __restrict__ dst, int npairs)
{
    int i = blockIdx.x * 256 + threadIdx.x;
    if (i < npairs) {
        float2 v = ((const float2*)src)[i];
        dst[i] = pack_bf2(v.x, v.y);
    }
}

// ---------------------------------------------------------------------------
// Kernel 1: zero-centered RMSNorm -> bf16 pairs
// thread t handles cols 4t..4t+3
// ---------------------------------------------------------------------------
__global__ __launch_bounds__(256) void rmsnorm_kernel(
    const float* __restrict__ x, const float* __restrict__ g,
    unsigned* __restrict__ hb)
{
    __shared__ float sbuf[8];
    int row = blockIdx.x;
    const float* xr = x + (size_t)row * PD;
    int t = threadIdx.x;
    float4 v = *(const float4*)(xr + 4 * t);
    float s = v.x + v.y + v.z + v.w;
    {
        int lane = t & 31, wid = t >> 5;
        #pragma unroll
        for (int o = 16; o > 0; o >>= 1) s += __shfl_xor_sync(0xffffffffu, s, o);
        if (lane == 0) sbuf[wid] = s;
        __syncthreads();
        s = 0.f;
        #pragma unroll
        for (int w = 0; w < 8; w++) s += sbuf[w];
    }
    float mean = s * (1.f / (float)PD);
    float c0 = v.x - mean, c1 = v.y - mean, c2 = v.z - mean, c3 = v.w - mean;
    float s2 = c0*c0 + c1*c1 + c2*c2 + c3*c3;
    __syncthreads();
    {
        int lane = t & 31, wid = t >> 5;
        #pragma unroll
        for (int o = 16; o > 0; o >>= 1) s2 += __shfl_xor_sync(0xffffffffu, s2, o);
        if (lane == 0) sbuf[wid] = s2;
        __syncthreads();
        s2 = 0.f;
        #pragma unroll
        for (int w = 0; w < 8; w++) s2 += sbuf[w];
    }
    float scale = rsqrtf(s2 * (1.f / (float)PD) + PEPS);
    float4 gv = *(const float4*)(g + 4 * t);
    unsigned p0 = pack_bf2(c0 * scale * gv.x, c1 * scale * gv.y);
    unsigned p1 = pack_bf2(c2 * scale * gv.z, c3 * scale * gv.w);
    *(uint2*)(hb + (size_t)row * 512 + 2 * t) = make_uint2(p0, p1);
}

// ---------------------------------------------------------------------------
// Kernel 2: bf16 tensor-core GEMM, 3-stage cp.async, BK=32.
// C[M,Nc] = A[M,K] * W[Nc,K]^T. A,W are bf16-pair (u32) arrays.
// EPI=0: C fp32 = acc + bias
// EPI=1: C fp32 = xres + sigmoid(acc+bias) * t1
// EPI=2: qkv split: cols<2048 -> qkh bf16 pairs; cols>=2048 -> vout fp32
// ---------------------------------------------------------------------------
#define SMS2 20     // u32 per row (16 used + 4 pad)
#define GSTG 3
#define GEMM_SMEM (GSTG * 128 * SMS2 * 2 * 4)   // 61440 B

template<int EPI>
__global__ __launch_bounds__(256) void mma_bf16(
    const unsigned* __restrict__ Ab, const unsigned* __restrict__ Wb,
    const float* __restrict__ bias, float* __restrict__ C,
    int M, int Nc, int K,
    const float* __restrict__ xres, const float* __restrict__ t1,
    unsigned* __restrict__ qkh, float* __restrict__ vout)
{
    extern __shared__ unsigned smg[];
    unsigned* As = smg;                        // [GSTG][128][SMS2]
    unsigned* Bs = smg + GSTG * 128 * SMS2;

    int tid = threadIdx.x, lane = tid & 31, wid = tid >> 5;
    int m0 = blockIdx.y * 128, n0 = blockIdx.x * 128;
    int wm = (wid & 1) * 64, wn = (wid >> 1) * 32;
    int gq = lane >> 2, gt = lane & 3;

    int lr = tid >> 1;          // row 0..127
    int half = tid & 1;         // which half of the 64B row

    float acc[4][4][4];
    #pragma unroll
    for (int mt = 0; mt < 4; mt++)
        #pragma unroll
        for (int nt = 0; nt < 4; nt++)
            #pragma unroll
            for (int c = 0; c < 4; c++) acc[mt][nt][c] = 0.f;

    bool aval = (m0 + lr) < M;
    int arow = aval ? (m0 + lr) : (M - 1);
    const int Kp = K >> 1;  // pairs per row
    const unsigned* Aptr = Ab + (size_t)arow * Kp;
    const unsigned* Wptr = Wb + (size_t)(n0 + lr) * Kp;
    int abytes = aval ? 16 : 0;

    const int steps = K >> 5;   // K/32

    // prologue
    #pragma unroll
    for (int s = 0; s < GSTG - 1; s++) {
        int kp0 = s * 16;   // pair offset of stage
        cp_async16(&As[(s * 128 + lr) * SMS2 + half * 8],     Aptr + kp0 + half * 8,     abytes);
        cp_async16(&As[(s * 128 + lr) * SMS2 + half * 8 + 4], Aptr + kp0 + half * 8 + 4, abytes);
        cp_async16(&Bs[(s * 128 + lr) * SMS2 + half * 8],     Wptr + kp0 + half * 8,     16);
        cp_async16(&Bs[(s * 128 + lr) * SMS2 + half * 8 + 4], Wptr + kp0 + half * 8 + 4, 16);
        cp_commit();
    }

    for (int i = 0; i < steps; i++) {
        cp_wait<GSTG - 2>();
        __syncthreads();

        int pf = i + GSTG - 1;
        if (pf < steps) {
            int s = pf % GSTG;
            int kp0 = pf * 16;
            cp_async16(&As[(s * 128 + lr) * SMS2 + half * 8],     Aptr + kp0 + half * 8,     abytes);
            cp_async16(&As[(s * 128 + lr) * SMS2 + half * 8 + 4], Aptr + kp0 + half * 8 + 4, abytes);
            cp_async16(&Bs[(s * 128 + lr) * SMS2 + half * 8],     Wptr + kp0 + half * 8,     16);
            cp_async16(&Bs[(s * 128 + lr) * SMS2 + half * 8 + 4], Wptr + kp0 + half * 8 + 4, 16);
        }
        cp_commit();

        const unsigned* Asb = As + (i % GSTG) * 128 * SMS2;
        const unsigned* Bsb = Bs + (i % GSTG) * 128 * SMS2;

        #pragma unroll
        for (int kk2 = 0; kk2 < 16; kk2 += 8) {   // two k16 steps (pair offsets 0, 8)
            unsigned af[4][4], bf[4][2];
            #pragma unroll
            for (int mt = 0; mt < 4; mt++) {
                int mm = wm + mt * 16 + gq;
                af[mt][0] = Asb[ mm      * SMS2 + kk2 + gt];
                af[mt][1] = Asb[(mm + 8) * SMS2 + kk2 + gt];
                af[mt][2] = Asb[ mm      * SMS2 + kk2 + gt + 4];
                af[mt][3] = Asb[(mm + 8) * SMS2 + kk2 + gt + 4];
            }
            #pragma unroll
            for (int nt = 0; nt < 4; nt++) {
                int nn = wn + nt * 8 + gq;
                bf[nt][0] = Bsb[nn * SMS2 + kk2 + gt];
                bf[nt][1] = Bsb[nn * SMS2 + kk2 + gt + 4];
            }
            #pragma unroll
            for (int mt = 0; mt < 4; mt++)
                #pragma unroll
                for (int nt = 0; nt < 4; nt++)
                    MMA_BF16(acc[mt][nt], af[mt][0], af[mt][1], af[mt][2], af[mt][3],
                             bf[nt][0], bf[nt][1]);
        }
    }

    #pragma unroll
    for (int mt = 0; mt < 4; mt++) {
        int r0 = m0 + wm + mt * 16 + gq;
        #pragma unroll
        for (int nt = 0; nt < 4; nt++) {
            int cb = n0 + wn + nt * 8 + gt * 2;
            float b0 = bias[cb], b1 = bias[cb + 1];
            #pragma unroll
            for (int hh = 0; hh < 2; hh++) {
                int r = r0 + hh * 8;
                if (r >= M) continue;
                float v0 = acc[mt][nt][hh * 2 + 0] + b0;
                float v1 = acc[mt][nt][hh * 2 + 1] + b1;
                if (EPI == 0) {
                    size_t off = (size_t)r * Nc + cb;
                    C[off] = v0; C[off + 1] = v1;
                } else if (EPI == 1) {
                    size_t off = (size_t)r * Nc + cb;
                    float g0 = 1.f / (1.f + __expf(-v0));
                    float g1 = 1.f / (1.f + __expf(-v1));
                    C[off]     = xres[off]     + g0 * t1[off];
                    C[off + 1] = xres[off + 1] + g1 * t1[off + 1];
                } else {
                    if (cb < 2048) {
                        qkh[(size_t)r * 1024 + (cb >> 1)] = pack_bf2(v0, v1);
                    } else {
                        size_t off = (size_t)r * 1024 + (cb - 2048);
                        vout[off] = v0; vout[off + 1] = v1;
                    }
                }
            }
        }
    }
}

// ---------------------------------------------------------------------------
// Kernel 3: RoPE on bf16 q,k pairs in g_qkh
// thread = (row, head, d2): q pair at row*1024 + h*32 + d2, k at +512
// ---------------------------------------------------------------------------
__global__ __launch_bounds__(256) void rope_kernel(
    unsigned* __restrict__ qkh, const float* __restrict__ fc)
{
    int idx = blockIdx.x * blockDim.x + threadIdx.x;
    const int total = PM * PH * (PDh / 2);
    if (idx >= total) return;
    int d2  = idx & 31;
    int h   = (idx >> 5) & 15;
    int row = idx >> 9;
    int n   = row % PN;
    float fr = fc[(n * 32 + d2) * 2 + 0];
    float fi = fc[(n * 32 + d2) * 2 + 1];
    size_t base = (size_t)row * 1024 + h * 32 + d2;
    unsigned q = qkh[base];
    float qr = bf_lo(q), qi = bf_hi(q);
    qkh[base] = pack_bf2(qr * fr - qi * fi, qr * fi + qi * fr);
    unsigned k = qkh[base + 512];
    float kr = bf_lo(k), ki = bf_hi(k);
    qkh[base + 512] = pack_bf2(kr * fr - ki * fi, kr * fi + ki * fr);
}

// ---------------------------------------------------------------------------
// Kernel 4: flash attention. S = QK^T in bf16 m16n8k16; PV in tf32 m16n8k8.
// Block 256 thr = 8 warps; q-tile 128, k-tile 64, double-buffered cp.async.
// smem: Ks u32[2][64][36] + Vs f32[2][64][72] + Ps f32[128][68] = 90112 B
// ---------------------------------------------------------------------------
#define KS2_STR 36
#define VS_STR 72
#define PS_STR 68
#define NKT ((PN + 63) / 64)
#define FLASH_SMEM ((2*64*KS2_STR + 2*64*VS_STR + 128*PS_STR) * 4)

__global__ __launch_bounds__(256) void flash_mma_kernel(
    const unsigned* __restrict__ qkh, const float* __restrict__ vg,
    const float* __restrict__ Bbias, unsigned* __restrict__ yh)
{
    extern __shared__ float sm[];
    unsigned* Ks = (unsigned*)sm;                       // [2][64][36] u32
    float* Vs = sm + 2 * 64 * KS2_STR;                  // [2][64][72] f32
    float* Ps = sm + 2 * 64 * KS2_STR + 2 * 64 * VS_STR; // [128][68]

    int b = blockIdx.z, h = blockIdx.y;
    int q0 = blockIdx.x * 128;
    int tid = threadIdx.x, lane = tid & 31, wid = tid >> 5;
    int gq = lane >> 2, gt = lane & 3;

    int wrow = wid * 16;
    int r1 = q0 + wrow + gq;
    int r2 = r1 + 8;
    bool r1ok = r1 < PN, r2ok = r2 < PN;

    const unsigned* qk_b = qkh + (size_t)b * PN * 1024;
    const float*    v_b  = vg  + (size_t)b * PN * 1024;

    int krow = tid >> 2;        // 0..63
    int sub  = tid & 3;         // 0..3

    // ---- prologue: stage 0 K (bf16) + V (fp32) ----
    {
        int gk = krow;
        int ok = (gk < PN) ? 16 : 0;
        const unsigned* ksrc = qk_b + (size_t)((gk < PN) ? gk : 0) * 1024 + 512 + h * 32;
        #pragma unroll
        for (int c = 0; c < 2; c++)
            cp_async16(&Ks[krow * KS2_STR + (sub * 2 + c) * 4], ksrc + (sub * 2 + c) * 4, ok);
        const float* vsrc = v_b + (size_t)((gk < PN) ? gk : 0) * 1024 + h * 64;
        #pragma unroll
        for (int c = 0; c < 4; c++)
            cp_async16(&Vs[krow * VS_STR + (sub * 4 + c) * 4], vsrc + (sub * 4 + c) * 4, ok);
        cp_commit();
    }

    // ---- Q fragments (bf16 pairs, no scale: folded into S) ----
    unsigned qf[4][4];
    {
        const unsigned* q1 = qk_b + (size_t)(r1ok ? r1 : 0) * 1024 + h * 32;
        const unsigned* q2 = qk_b + (size_t)(r2ok ? r2 : 0) * 1024 + h * 32;
        #pragma unroll
        for (int ks = 0; ks < 4; ks++) {
            qf[ks][0] = r1ok ? __ldg(q1 + 8 * ks + gt)     : 0u;
            qf[ks][1] = r2ok ? __ldg(q2 + 8 * ks + gt)     : 0u;
            qf[ks][2] = r1ok ? __ldg(q1 + 8 * ks + gt + 4) : 0u;
            qf[ks][3] = r2ok ? __ldg(q2 + 8 * ks + gt + 4) : 0u;
        }
    }

    float oacc[8][4];
    #pragma unroll
    for (int nt = 0; nt < 8; nt++)
        #pragma unroll
        for (int c = 0; c < 4; c++) oacc[nt][c] = 0.f;
    float m1 = -1e30f, m2 = -1e30f, l1 = 0.f, l2 = 0.f;

    const float* bb1 = Bbias + (size_t)(r1ok ? r1 : 0) * PN;
    const float* bb2 = Bbias + (size_t)(r2ok ? r2 : 0) * PN;

    for (int it = 0; it < NKT; it++) {
        int k0 = it * 64;
        cp_wait<0>();
        __syncthreads();

        // prefetch next stage
        if (it + 1 < NKT) {
            int s = (it + 1) & 1;
            int gk = (it + 1) * 64 + krow;
            int ok = (gk < PN) ? 16 : 0;
            const unsigned* ksrc = qk_b + (size_t)((gk < PN) ? gk : 0) * 1024 + 512 + h * 32;
            #pragma unroll
            for (int c = 0; c < 2; c++)
                cp_async16(&Ks[(s * 64 + krow) * KS2_STR + (sub * 2 + c) * 4],
                           ksrc + (sub * 2 + c) * 4, ok);
            const float* vsrc = v_b + (size_t)((gk < PN) ? gk : 0) * 1024 + h * 64;
            #pragma unroll
            for (int c = 0; c < 4; c++)
                cp_async16(&Vs[(s * 64 + krow) * VS_STR + (sub * 4 + c) * 4],
                           vsrc + (sub * 4 + c) * 4, ok);
        }
        cp_commit();

        const unsigned* Ksb = Ks + (it & 1) * 64 * KS2_STR;
        const float*    Vsb = Vs + (it & 1) * 64 * VS_STR;

        // ---- S = Q K^T (bf16, 4 k-steps of 16) ----
        float sacc[8][4];
        #pragma unroll
        for (int nt = 0; nt < 8; nt++)
            #pragma unroll
            for (int c = 0; c < 4; c++) sacc[nt][c] = 0.f;

        #pragma unroll
        for (int ks = 0; ks < 4; ks++) {
            #pragma unroll
            for (int nt = 0; nt < 8; nt++) {
                unsigned b0 = Ksb[(nt * 8 + gq) * KS2_STR + 8 * ks + gt];
                unsigned b1 = Ksb[(nt * 8 + gq) * KS2_STR + 8 * ks + gt + 4];
                MMA_BF16(sacc[nt], qf[ks][0], qf[ks][1], qf[ks][2], qf[ks][3], b0, b1);
            }
        }

        // ---- scale + bias + mask + row max ----
        float mx1 = -1e30f, mx2 = -1e30f;
        #pragma unroll
        for (int nt = 0; nt < 8; nt++) {
            int gc0 = k0 + nt * 8 + gt * 2;
            int gc1 = gc0 + 1;
            bool c0ok = gc0 < PN, c1ok = gc1 < PN;
            sacc[nt][0] = (r1ok && c0ok) ? fmaf(sacc[nt][0], 0.125f, __ldg(bb1 + gc0)) : -1e30f;
            sacc[nt][1] = (r1ok && c1ok) ? fmaf(sacc[nt][1], 0.125f, __ldg(bb1 + gc1)) : -1e30f;
            sacc[nt][2] = (r2ok && c0ok) ? fmaf(sacc[nt][2], 0.125f, __ldg(bb2 + gc0)) : -1e30f;
            sacc[nt][3] = (r2ok && c1ok) ? fmaf(sacc[nt][3], 0.125f, __ldg(bb2 + gc1)) : -1e30f;
            mx1 = fmaxf(mx1, fmaxf(sacc[nt][0], sacc[nt][1]));
            mx2 = fmaxf(mx2, fmaxf(sacc[nt][2], sacc[nt][3]));
        }
        mx1 = fmaxf(mx1, __shfl_xor_sync(0xffffffffu, mx1, 1));
        mx1 = fmaxf(mx1, __shfl_xor_sync(0xffffffffu, mx1, 2));
        mx2 = fmaxf(mx2, __shfl_xor_sync(0xffffffffu, mx2, 1));
        mx2 = fmaxf(mx2, __shfl_xor_sync(0xffffffffu, mx2, 2));

        float mn1 = fmaxf(m1, mx1), mn2 = fmaxf(m2, mx2);
        float corr1 = __expf(m1 - mn1), corr2 = __expf(m2 - mn2);
        m1 = mn1; m2 = mn2;

        // ---- exp, row sums, store P (tf32) ----
        float sum1 = 0.f, sum2 = 0.f;
        #pragma unroll
        for (int nt = 0; nt < 8; nt++) {
            float p0 = __expf(sacc[nt][0] - m1);
            float p1 = __expf(sacc[nt][1] - m1);
            float p2 = __expf(sacc[nt][2] - m2);
            float p3 = __expf(sacc[nt][3] - m2);
            sum1 += p0 + p1; sum2 += p2 + p3;
            int col = nt * 8 + gt * 2;
            *(float2*)&Ps[(wrow + gq)     * PS_STR + col] = make_float2(to_tf32(p0), to_tf32(p1));
            *(float2*)&Ps[(wrow + gq + 8) * PS_STR + col] = make_float2(to_tf32(p2), to_tf32(p3));
        }
        sum1 += __shfl_xor_sync(0xffffffffu, sum1, 1);
        sum1 += __shfl_xor_sync(0xffffffffu, sum1, 2);
        sum2 += __shfl_xor_sync(0xffffffffu, sum2, 1);
        sum2 += __shfl_xor_sync(0xffffffffu, sum2, 2);
        l1 = l1 * corr1 + sum1;
        l2 = l2 * corr2 + sum2;

        #pragma unroll
        for (int nt = 0; nt < 8; nt++) {
            oacc[nt][0] *= corr1; oacc[nt][1] *= corr1;
            oacc[nt][2] *= corr2; oacc[nt][3] *= corr2;
        }
        __syncwarp();   // Ps is warp-private

        // ---- O += P V (tf32) ----
        #pragma unroll
        for (int ks = 0; ks < 8; ks++) {
            int kk = ks * 8;
            unsigned a0 = __float_as_uint(Ps[(wrow + gq)     * PS_STR + kk + gt]);
            unsigned a1 = __float_as_uint(Ps[(wrow + gq + 8) * PS_STR + kk + gt]);
            unsigned a2 = __float_as_uint(Ps[(wrow + gq)     * PS_STR + kk + gt + 4]);
            unsigned a3 = __float_as_uint(Ps[(wrow + gq + 8) * PS_STR + kk + gt + 4]);
            #pragma unroll
            for (int nt = 0; nt < 8; nt++) {
                unsigned b0 = __float_as_uint(Vsb[(kk + gt)     * VS_STR + nt * 8 + gq]);
                unsigned b1 = __float_as_uint(Vsb[(kk + gt + 4) * VS_STR + nt * 8 + gq]);
                MMA_TF32(oacc[nt], a0, a1, a2, a3, b0, b1);
            }
        }
    }

    // ---- epilogue: normalize, pack bf16, write yh[b, q, (h*64+d)/2] ----
    float inv1 = 1.f / l1, inv2 = 1.f / l2;
    #pragma unroll
    for (int nt = 0; nt < 8; nt++) {
        int colp = h * 32 + (nt * 8 + gt * 2) / 2;   // pair index
        if (r1ok)
            yh[((size_t)(b * PN + r1)) * 512 + colp] =
                pack_bf2(oacc[nt][0] * inv1, oacc[nt][1] * inv1);
        if (r2ok)
            yh[((size_t)(b * PN + r2)) * 512 + colp] =
                pack_bf2(oacc[nt][2] * inv2, oacc[nt][3] * inv2);
    }
}

// ---------------------------------------------------------------------------
// Launch
// ---------------------------------------------------------------------------
extern "C" void kernel_launch(void* const* d_in, const int* in_sizes, int n_in,
                              void* d_out, int out_size)
{
    (void)in_sizes; (void)n_in; (void)out_size;
    const float* x      = (const float*)d_in[0];
    const float* fc     = (const float*)d_in[1];
    const float* g      = (const float*)d_in[2];
    const float* qkv_w  = (const float*)d_in[3];
    const float* qkv_b  = (const float*)d_in[4];
    const float* out_w  = (const float*)d_in[5];
    const float* out_b  = (const float*)d_in[6];
    const float* gate_w = (const float*)d_in[7];
    const float* gate_b = (const float*)d_in[8];
    const float* Bbias  = (const float*)d_in[9];
    float* out = (float*)d_out;

    unsigned *hb, *qkh, *yh, *wqkv, *wout, *wgate;
    float *v, *t1;
    cudaGetSymbolAddress((void**)&hb,    g_hb);
    cudaGetSymbolAddress((void**)&qkh,   g_qkh);
    cudaGetSymbolAddress((void**)&v,     g_v);
    cudaGetSymbolAddress((void**)&yh,    g_yh);
    cudaGetSymbolAddress((void**)&t1,    g_t1);
    cudaGetSymbolAddress((void**)&wqkv,  g_wqkv);
    cudaGetSymbolAddress((void**)&wout,  g_wout);
    cudaGetSymbolAddress((void**)&wgate, g_wgate);

    cudaFuncSetAttribute(mma_bf16<0>, cudaFuncAttributeMaxDynamicSharedMemorySize, GEMM_SMEM);
    cudaFuncSetAttribute(mma_bf16<1>, cudaFuncAttributeMaxDynamicSharedMemorySize, GEMM_SMEM);
    cudaFuncSetAttribute(mma_bf16<2>, cudaFuncAttributeMaxDynamicSharedMemorySize, GEMM_SMEM);
    cudaFuncSetAttribute(flash_mma_kernel,
                         cudaFuncAttributeMaxDynamicSharedMemorySize, FLASH_SMEM);

    // 0. weight conversions (bf16)
    cvt_bf16_kernel<<<(3072 * 512 + 255) / 256, 256>>>(qkv_w,  wqkv,  3072 * 512);
    cvt_bf16_kernel<<<(1024 * 512 + 255) / 256, 256>>>(out_w,  wout,  1024 * 512);
    cvt_bf16_kernel<<<(1024 * 512 + 255) / 256, 256>>>(gate_w, wgate, 1024 * 512);

    // 1. zero-centered RMSNorm -> bf16
    rmsnorm_kernel<<<PM, 256>>>(x, g, hb);

    // 2. QKV projection (bf16): q,k -> g_qkh bf16, v -> g_v fp32
    dim3 g1(3072 / 128, (PM + 127) / 128);
    mma_bf16<2><<<g1, 256, GEMM_SMEM>>>(hb, wqkv, qkv_b, nullptr, PM, 3072, PD,
                                        nullptr, nullptr, qkh, v);

    // 3. RoPE on bf16 q,k
    int nrope = PM * PH * (PDh / 2);
    rope_kernel<<<(nrope + 255) / 256, 256>>>(qkh, fc);

    // 4. flash attention (S bf16, PV tf32) -> yh bf16
    flash_mma_kernel<<<dim3((PN + 127) / 128, PH, PB), 256, FLASH_SMEM>>>(qkh, v, Bbias, yh);

    // 5. out projection: t1 = y @ out_w^T + out_b  (fp32 out)
    dim3 g2(PD / 128, (PM + 127) / 128);
    mma_bf16<0><<<g2, 256, GEMM_SMEM>>>(yh, wout, out_b, t1, PM, PD, PD,
                                        nullptr, nullptr, nullptr, nullptr);

    // 6. gated residual: out = x + sigmoid(h @ gate_w^T + gate_b) * t1
    mma_bf16<1><<<g2, 256, GEMM_SMEM>>>(hb, wgate, gate_b, out, PM, PD, PD,
                                        x, t1, nullptr, nullptr);
}

// round 12
// speedup vs baseline: 1.0777x; 1.0777x over previous
#include <cuda_runtime.h>
#include <math.h>

// Problem constants
#define PB 8
#define PN 1025
#define PD 1024
#define PH 16
#define PDh 64
#define PM (PB*PN)      // 8200 rows
#define PEPS 1e-8f

// Scratch (device globals: allocation-free rule)
__device__ float g_h  [(size_t)PM * PD];    // rmsnorm output
__device__ float g_qkv[(size_t)PM * 3 * PD];// qkv (rope fused into epilogue)
__device__ float g_y  [(size_t)PM * PD];    // attention output
__device__ float g_sig[(size_t)PM * PD];    // sigmoid(gate) buffer

__device__ __forceinline__ float to_tf32(float x) {
    float r;
    asm("cvt.rna.tf32.f32 %0, %1;" : "=f"(r) : "f"(x));
    return r;
}

// cp.async helpers
__device__ __forceinline__ void cp_async16(void* smem_dst, const void* gmem_src, int src_bytes) {
    unsigned saddr = (unsigned)__cvta_generic_to_shared(smem_dst);
    asm volatile("cp.async.cg.shared.global [%0], [%1], 16, %2;\n"
                 :: "r"(saddr), "l"(gmem_src), "r"(src_bytes));
}
__device__ __forceinline__ void cp_commit() {
    asm volatile("cp.async.commit_group;\n" ::);
}
template<int N>
__device__ __forceinline__ void cp_wait() {
    asm volatile("cp.async.wait_group %0;\n" :: "n"(N));
}

#define MMA_TF32(c, a0,a1,a2,a3, b0,b1) \
    asm volatile("mma.sync.aligned.m16n8k8.row.col.f32.tf32.tf32.f32 " \
        "{%0,%1,%2,%3}, {%4,%5,%6,%7}, {%8,%9}, {%0,%1,%2,%3};" \
        : "+f"((c)[0]), "+f"((c)[1]), "+f"((c)[2]), "+f"((c)[3]) \
        : "r"(a0), "r"(a1), "r"(a2), "r"(a3), "r"(b0), "r"(b1))

// ---------------------------------------------------------------------------
// Kernel 1: zero-centered RMSNorm (fp32 out) — proven R7 version
// ---------------------------------------------------------------------------
__global__ __launch_bounds__(256) void rmsnorm_kernel(
    const float* __restrict__ x, const float* __restrict__ g,
    float* __restrict__ h)
{
    __shared__ float sbuf[8];
    int row = blockIdx.x;
    const float* xr = x + (size_t)row * PD;
    int t = threadIdx.x;
    float v[4];
    float s = 0.f;
    #pragma unroll
    for (int i = 0; i < 4; i++) { v[i] = xr[i * 256 + t]; s += v[i]; }
    {
        int lane = t & 31, wid = t >> 5;
        #pragma unroll
        for (int o = 16; o > 0; o >>= 1) s += __shfl_xor_sync(0xffffffffu, s, o);
        if (lane == 0) sbuf[wid] = s;
        __syncthreads();
        s = 0.f;
        #pragma unroll
        for (int w = 0; w < 8; w++) s += sbuf[w];
    }
    float mean = s * (1.f / (float)PD);
    float s2 = 0.f;
    #pragma unroll
    for (int i = 0; i < 4; i++) { float c = v[i] - mean; s2 += c * c; }
    __syncthreads();
    {
        int lane = t & 31, wid = t >> 5;
        #pragma unroll
        for (int o = 16; o > 0; o >>= 1) s2 += __shfl_xor_sync(0xffffffffu, s2, o);
        if (lane == 0) sbuf[wid] = s2;
        __syncthreads();
        s2 = 0.f;
        #pragma unroll
        for (int w = 0; w < 8; w++) s2 += sbuf[w];
    }
    float scale = rsqrtf(s2 * (1.f / (float)PD) + PEPS);
    float* hr = h + (size_t)row * PD;
    #pragma unroll
    for (int i = 0; i < 4; i++)
        hr[i * 256 + t] = (v[i] - mean) * scale * g[i * 256 + t];
}

// ---------------------------------------------------------------------------
// tf32 GEMM body (R7-proven): C[M,Nc] = A[M,K] * W[Nc,K]^T, 128x128 tile,
// BK=16, 3-stage cp.async, 8 warps x (64x32).
// EPI=0: C = acc + bias
// EPI=2: QKV + fused rope on cols < 2048
// EPI=3: final: C = xres + sig * (acc + bias)
// EPI=4: C = sigmoid(acc + bias)
// ---------------------------------------------------------------------------
#define SMS 20
#define GSTG 3
#define GEMM_SMEM (GSTG * 128 * SMS * 2 * 4)   // 61440 B

template<int EPI>
__device__ __forceinline__ void gemm_body(
    char* smraw, int m0, int n0,
    const float* __restrict__ A, const float* __restrict__ W,
    const float* __restrict__ bias, float* __restrict__ C,
    int M, int Nc, int K,
    const float* __restrict__ xres, const float* __restrict__ sig,
    const float* __restrict__ fc)
{
    float* As = (float*)smraw;             // [GSTG][128][SMS]
    float* Bs = As + GSTG * 128 * SMS;

    int tid = threadIdx.x, lane = tid & 31, wid = tid >> 5;
    int wm = (wid & 1) * 64, wn = (wid >> 1) * 32;

    int lr = tid >> 1;
    int lk = (tid & 1) * 8;
    int gq = lane >> 2, gt = lane & 3;

    float acc[4][4][4];
    #pragma unroll
    for (int mt = 0; mt < 4; mt++)
        #pragma unroll
        for (int nt = 0; nt < 4; nt++)
            #pragma unroll
            for (int c = 0; c < 4; c++) acc[mt][nt][c] = 0.f;

    bool aval = (m0 + lr) < M;
    int arow = aval ? (m0 + lr) : (M - 1);
    const float* Aptr = A + (size_t)arow * K + lk;
    const float* Wptr = W + (size_t)(n0 + lr) * K + lk;
    int abytes = aval ? 16 : 0;

    const int steps = K >> 4;

    #pragma unroll
    for (int s = 0; s < GSTG - 1; s++) {
        int k0 = s * 16;
        cp_async16(&As[(s * 128 + lr) * SMS + lk],     Aptr + k0,     abytes);
        cp_async16(&As[(s * 128 + lr) * SMS + lk + 4], Aptr + k0 + 4, abytes);
        cp_async16(&Bs[(s * 128 + lr) * SMS + lk],     Wptr + k0,     16);
        cp_async16(&Bs[(s * 128 + lr) * SMS + lk + 4], Wptr + k0 + 4, 16);
        cp_commit();
    }

    for (int i = 0; i < steps; i++) {
        cp_wait<GSTG - 2>();
        __syncthreads();

        int pf = i + GSTG - 1;
        if (pf < steps) {
            int s = pf % GSTG;
            int k0 = pf * 16;
            cp_async16(&As[(s * 128 + lr) * SMS + lk],     Aptr + k0,     abytes);
            cp_async16(&As[(s * 128 + lr) * SMS + lk + 4], Aptr + k0 + 4, abytes);
            cp_async16(&Bs[(s * 128 + lr) * SMS + lk],     Wptr + k0,     16);
            cp_async16(&Bs[(s * 128 + lr) * SMS + lk + 4], Wptr + k0 + 4, 16);
        }
        cp_commit();

        const float* Asb = As + (i % GSTG) * 128 * SMS;
        const float* Bsb = Bs + (i % GSTG) * 128 * SMS;

        #pragma unroll
        for (int kk = 0; kk < 16; kk += 8) {
            unsigned af[4][4], bf[4][2];
            #pragma unroll
            for (int mt = 0; mt < 4; mt++) {
                int mm = wm + mt * 16 + gq;
                af[mt][0] = __float_as_uint(Asb[ mm      * SMS + kk + gt]);
                af[mt][1] = __float_as_uint(Asb[(mm + 8) * SMS + kk + gt]);
                af[mt][2] = __float_as_uint(Asb[ mm      * SMS + kk + gt + 4]);
                af[mt][3] = __float_as_uint(Asb[(mm + 8) * SMS + kk + gt + 4]);
            }
            #pragma unroll
            for (int nt = 0; nt < 4; nt++) {
                int nn = wn + nt * 8 + gq;
                bf[nt][0] = __float_as_uint(Bsb[nn * SMS + kk + gt]);
                bf[nt][1] = __float_as_uint(Bsb[nn * SMS + kk + gt + 4]);
            }
            #pragma unroll
            for (int mt = 0; mt < 4; mt++)
                #pragma unroll
                for (int nt = 0; nt < 4; nt++)
                    MMA_TF32(acc[mt][nt], af[mt][0], af[mt][1], af[mt][2], af[mt][3],
                             bf[nt][0], bf[nt][1]);
        }
    }

    #pragma unroll
    for (int mt = 0; mt < 4; mt++) {
        int r0 = m0 + wm + mt * 16 + gq;
        #pragma unroll
        for (int nt = 0; nt < 4; nt++) {
            int cb = n0 + wn + nt * 8 + gt * 2;
            float b0 = bias[cb], b1 = bias[cb + 1];
            #pragma unroll
            for (int hh = 0; hh < 2; hh++) {
                int r = r0 + hh * 8;
                if (r >= M) continue;
                size_t off = (size_t)r * Nc + cb;
                float v0 = acc[mt][nt][hh * 2 + 0] + b0;
                float v1 = acc[mt][nt][hh * 2 + 1] + b1;
                if (EPI == 0) {
                    C[off] = v0; C[off + 1] = v1;
                } else if (EPI == 2) {
                    if (cb < 2048) {
                        int n  = r % PN;
                        int d2 = (cb & 63) >> 1;
                        float2 f = *(const float2*)&fc[(size_t)(n * 32 + d2) * 2];
                        C[off]     = v0 * f.x - v1 * f.y;
                        C[off + 1] = v0 * f.y + v1 * f.x;
                    } else {
                        C[off] = v0; C[off + 1] = v1;
                    }
                } else if (EPI == 3) {
                    C[off]     = xres[off]     + sig[off]     * v0;
                    C[off + 1] = xres[off + 1] + sig[off + 1] * v1;
                } else {  // EPI == 4
                    C[off]     = 1.f / (1.f + __expf(-v0));
                    C[off + 1] = 1.f / (1.f + __expf(-v1));
                }
            }
        }
    }
}

template<int EPI>
__global__ __launch_bounds__(256) void mma_nt(
    const float* __restrict__ A, const float* __restrict__ W,
    const float* __restrict__ bias, float* __restrict__ C,
    int M, int Nc, int K,
    const float* __restrict__ xres, const float* __restrict__ sig,
    const float* __restrict__ fc)
{
    extern __shared__ char smraw[];
    gemm_body<EPI>(smraw, blockIdx.y * 128, blockIdx.x * 128,
                   A, W, bias, C, M, Nc, K, xres, sig, fc);
}

// ---------------------------------------------------------------------------
// Flash attention body (R7-proven): tf32 m16n8k8, q-tile 128, k-tile 64,
// double-buffered cp.async K/V, one __syncthreads per tile.
// ---------------------------------------------------------------------------
#define KS_STR 68
#define VS_STR 72
#define PS_STR 68
#define NKT ((PN + 63) / 64)
#define FLASH_SMEM ((2*64*KS_STR + 2*64*VS_STR + 128*PS_STR) * 4)   // 106496

__device__ __forceinline__ void flash_body(
    float* sm, const float* __restrict__ qkv, const float* __restrict__ Bbias,
    float* __restrict__ y, int b, int h, int q0)
{
    float* Ks = sm;
    float* Vs = sm + 2 * 64 * KS_STR;
    float* Ps = sm + 2 * 64 * KS_STR + 2 * 64 * VS_STR;

    int tid = threadIdx.x, lane = tid & 31, wid = tid >> 5;
    int gq = lane >> 2, gt = lane & 3;

    int wrow = wid * 16;
    int r1 = q0 + wrow + gq;
    int r2 = r1 + 8;
    bool r1ok = r1 < PN, r2ok = r2 < PN;

    const float* qkv_bh = qkv + ((size_t)b * PN) * 3072 + h * 64;

    {
        for (int i = tid; i < 64 * 16; i += 256) {
            int kr = i >> 4, dg = (i & 15) << 2;
            int gk = kr;
            int ok = (gk < PN) ? 16 : 0;
            const float* base = qkv_bh + (size_t)((gk < PN) ? gk : (PN - 1)) * 3072 + dg;
            cp_async16(&Ks[kr * KS_STR + dg], base + 1024, ok);
            cp_async16(&Vs[kr * VS_STR + dg], base + 2048, ok);
        }
        cp_commit();
    }

    unsigned qf[8][4];
    {
        const float* q1 = qkv_bh + (size_t)(r1ok ? r1 : 0) * 3072;
        const float* q2 = qkv_bh + (size_t)(r2ok ? r2 : 0) * 3072;
        #pragma unroll
        for (int ks = 0; ks < 8; ks++) {
            int c0 = ks * 8 + gt, c1 = c0 + 4;
            qf[ks][0] = r1ok ? __float_as_uint(to_tf32(__ldg(q1 + c0) * 0.125f)) : 0u;
            qf[ks][1] = r2ok ? __float_as_uint(to_tf32(__ldg(q2 + c0) * 0.125f)) : 0u;
            qf[ks][2] = r1ok ? __float_as_uint(to_tf32(__ldg(q1 + c1) * 0.125f)) : 0u;
            qf[ks][3] = r2ok ? __float_as_uint(to_tf32(__ldg(q2 + c1) * 0.125f)) : 0u;
        }
    }

    float oacc[8][4];
    #pragma unroll
    for (int nt = 0; nt < 8; nt++)
        #pragma unroll
        for (int c = 0; c < 4; c++) oacc[nt][c] = 0.f;
    float m1 = -1e30f, m2 = -1e30f, l1 = 0.f, l2 = 0.f;

    const float* bb1 = Bbias + (size_t)(r1ok ? r1 : 0) * PN;
    const float* bb2 = Bbias + (size_t)(r2ok ? r2 : 0) * PN;

    for (int it = 0; it < NKT; it++) {
        int k0 = it * 64;
        cp_wait<0>();
        __syncthreads();

        if (it + 1 < NKT) {
            int s = (it + 1) & 1;
            int nk0 = (it + 1) * 64;
            for (int i = tid; i < 64 * 16; i += 256) {
                int kr = i >> 4, dg = (i & 15) << 2;
                int gk = nk0 + kr;
                int ok = (gk < PN) ? 16 : 0;
                const float* base = qkv_bh + (size_t)((gk < PN) ? gk : (PN - 1)) * 3072 + dg;
                cp_async16(&Ks[(s * 64 + kr) * KS_STR + dg], base + 1024, ok);
                cp_async16(&Vs[(s * 64 + kr) * VS_STR + dg], base + 2048, ok);
            }
        }
        cp_commit();

        const float* Ksb = Ks + (it & 1) * 64 * KS_STR;
        const float* Vsb = Vs + (it & 1) * 64 * VS_STR;

        float sacc[8][4];
        #pragma unroll
        for (int nt = 0; nt < 8; nt++)
            #pragma unroll
            for (int c = 0; c < 4; c++) sacc[nt][c] = 0.f;

        #pragma unroll
        for (int ks = 0; ks < 8; ks++) {
            int kk = ks * 8;
            #pragma unroll
            for (int nt = 0; nt < 8; nt++) {
                unsigned b0 = __float_as_uint(to_tf32(Ksb[(nt * 8 + gq) * KS_STR + kk + gt]));
                unsigned b1 = __float_as_uint(to_tf32(Ksb[(nt * 8 + gq) * KS_STR + kk + gt + 4]));
                MMA_TF32(sacc[nt], qf[ks][0], qf[ks][1], qf[ks][2], qf[ks][3], b0, b1);
            }
        }

        float mx1 = -1e30f, mx2 = -1e30f;
        #pragma unroll
        for (int nt = 0; nt < 8; nt++) {
            int gc0 = k0 + nt * 8 + gt * 2;
            int gc1 = gc0 + 1;
            bool c0ok = gc0 < PN, c1ok = gc1 < PN;
            sacc[nt][0] = (r1ok && c0ok) ? sacc[nt][0] + __ldg(bb1 + gc0) : -1e30f;
            sacc[nt][1] = (r1ok && c1ok) ? sacc[nt][1] + __ldg(bb1 + gc1) : -1e30f;
            sacc[nt][2] = (r2ok && c0ok) ? sacc[nt][2] + __ldg(bb2 + gc0) : -1e30f;
            sacc[nt][3] = (r2ok && c1ok) ? sacc[nt][3] + __ldg(bb2 + gc1) : -1e30f;
            mx1 = fmaxf(mx1, fmaxf(sacc[nt][0], sacc[nt][1]));
            mx2 = fmaxf(mx2, fmaxf(sacc[nt][2], sacc[nt][3]));
        }
        mx1 = fmaxf(mx1, __shfl_xor_sync(0xffffffffu, mx1, 1));
        mx1 = fmaxf(mx1, __shfl_xor_sync(0xffffffffu, mx1, 2));
        mx2 = fmaxf(mx2, __shfl_xor_sync(0xffffffffu, mx2, 1));
        mx2 = fmaxf(mx2, __shfl_xor_sync(0xffffffffu, mx2, 2));

        float mn1 = fmaxf(m1, mx1), mn2 = fmaxf(m2, mx2);
        float corr1 = __expf(m1 - mn1), corr2 = __expf(m2 - mn2);
        m1 = mn1; m2 = mn2;

        float sum1 = 0.f, sum2 = 0.f;
        #pragma unroll
        for (int nt = 0; nt < 8; nt++) {
            float p0 = __expf(sacc[nt][0] - m1);
            float p1 = __expf(sacc[nt][1] - m1);
            float p2 = __expf(sacc[nt][2] - m2);
            float p3 = __expf(sacc[nt][3] - m2);
            sum1 += p0 + p1; sum2 += p2 + p3;
            int col = nt * 8 + gt * 2;
            *(float2*)&Ps[(wrow + gq)     * PS_STR + col] = make_float2(to_tf32(p0), to_tf32(p1));
            *(float2*)&Ps[(wrow + gq + 8) * PS_STR + col] = make_float2(to_tf32(p2), to_tf32(p3));
        }
        sum1 += __shfl_xor_sync(0xffffffffu, sum1, 1);
        sum1 += __shfl_xor_sync(0xffffffffu, sum1, 2);
        sum2 += __shfl_xor_sync(0xffffffffu, sum2, 1);
        sum2 += __shfl_xor_sync(0xffffffffu, sum2, 2);
        l1 = l1 * corr1 + sum1;
        l2 = l2 * corr2 + sum2;

        #pragma unroll
        for (int nt = 0; nt < 8; nt++) {
            oacc[nt][0] *= corr1; oacc[nt][1] *= corr1;
            oacc[nt][2] *= corr2; oacc[nt][3] *= corr2;
        }
        __syncwarp();

        #pragma unroll
        for (int ks = 0; ks < 8; ks++) {
            int kk = ks * 8;
            unsigned a0 = __float_as_uint(Ps[(wrow + gq)     * PS_STR + kk + gt]);
            unsigned a1 = __float_as_uint(Ps[(wrow + gq + 8) * PS_STR + kk + gt]);
            unsigned a2 = __float_as_uint(Ps[(wrow + gq)     * PS_STR + kk + gt + 4]);
            unsigned a3 = __float_as_uint(Ps[(wrow + gq + 8) * PS_STR + kk + gt + 4]);
            #pragma unroll
            for (int nt = 0; nt < 8; nt++) {
                unsigned b0 = __float_as_uint(to_tf32(Vsb[(kk + gt)     * VS_STR + nt * 8 + gq]));
                unsigned b1 = __float_as_uint(to_tf32(Vsb[(kk + gt + 4) * VS_STR + nt * 8 + gq]));
                MMA_TF32(oacc[nt], a0, a1, a2, a3, b0, b1);
            }
        }
    }

    float inv1 = 1.f / l1, inv2 = 1.f / l2;
    #pragma unroll
    for (int nt = 0; nt < 8; nt++) {
        int col = h * 64 + nt * 8 + gt * 2;
        if (r1ok) {
            float* dst = y + ((size_t)(b * PN + r1)) * PD + col;
            dst[0] = oacc[nt][0] * inv1;
            dst[1] = oacc[nt][1] * inv1;
        }
        if (r2ok) {
            float* dst = y + ((size_t)(b * PN + r2)) * PD + col;
            dst[0] = oacc[nt][2] * inv2;
            dst[1] = oacc[nt][3] * inv2;
        }
    }
}

// ---------------------------------------------------------------------------
// Combined kernel: blocks [0,1152) = flash; blocks [1152,1672) = gate GEMM
// (sig = sigmoid(h @ gate_w^T + gate_b)). One launch => overlap on-chip.
// ---------------------------------------------------------------------------
#define FLASH_BLOCKS (((PN + 127) / 128) * PH * PB)    // 9*16*8 = 1152
#define GATE_BLOCKS  ((PD / 128) * ((PM + 127) / 128)) // 8*65  = 520

__global__ __launch_bounds__(256, 2) void flash_gate_kernel(
    const float* __restrict__ qkv, const float* __restrict__ Bbias,
    float* __restrict__ y,
    const float* __restrict__ h, const float* __restrict__ gate_w,
    const float* __restrict__ gate_b, float* __restrict__ sig)
{
    extern __shared__ char smraw[];
    int bid = blockIdx.x;
    if (bid < FLASH_BLOCKS) {
        int qt = bid % 9;
        int hh = (bid / 9) % PH;
        int bb = bid / (9 * PH);
        flash_body((float*)smraw, qkv, Bbias, y, bb, hh, qt * 128);
    } else {
        int gid = bid - FLASH_BLOCKS;
        int n0 = (gid % (PD / 128)) * 128;
        int m0 = (gid / (PD / 128)) * 128;
        gemm_body<4>(smraw, m0, n0, h, gate_w, gate_b, sig,
                     PM, PD, PD, nullptr, nullptr, nullptr);
    }
}

// ---------------------------------------------------------------------------
// Launch
// ---------------------------------------------------------------------------
extern "C" void kernel_launch(void* const* d_in, const int* in_sizes, int n_in,
                              void* d_out, int out_size)
{
    (void)in_sizes; (void)n_in; (void)out_size;
    const float* x      = (const float*)d_in[0];
    const float* fc     = (const float*)d_in[1];
    const float* g      = (const float*)d_in[2];
    const float* qkv_w  = (const float*)d_in[3];
    const float* qkv_b  = (const float*)d_in[4];
    const float* out_w  = (const float*)d_in[5];
    const float* out_b  = (const float*)d_in[6];
    const float* gate_w = (const float*)d_in[7];
    const float* gate_b = (const float*)d_in[8];
    const float* Bbias  = (const float*)d_in[9];
    float* out = (float*)d_out;

    float *h, *qkv, *y, *sig;
    cudaGetSymbolAddress((void**)&h,   g_h);
    cudaGetSymbolAddress((void**)&qkv, g_qkv);
    cudaGetSymbolAddress((void**)&y,   g_y);
    cudaGetSymbolAddress((void**)&sig, g_sig);

    cudaFuncSetAttribute(mma_nt<2>, cudaFuncAttributeMaxDynamicSharedMemorySize, GEMM_SMEM);
    cudaFuncSetAttribute(mma_nt<3>, cudaFuncAttributeMaxDynamicSharedMemorySize, GEMM_SMEM);
    cudaFuncSetAttribute(flash_gate_kernel,
                         cudaFuncAttributeMaxDynamicSharedMemorySize, FLASH_SMEM);

    // 1. zero-centered RMSNorm (fp32)
    rmsnorm_kernel<<<PM, 256>>>(x, g, h);

    // 2. QKV projection with fused RoPE epilogue
    dim3 g1(3072 / 128, (PM + 127) / 128);
    mma_nt<2><<<g1, 256, GEMM_SMEM>>>(h, qkv_w, qkv_b, qkv, PM, 3072, PD,
                                      nullptr, nullptr, fc);

    // 3. flash attention + gate GEMM fused into one launch (overlap)
    flash_gate_kernel<<<FLASH_BLOCKS + GATE_BLOCKS, 256, FLASH_SMEM>>>(
        qkv, Bbias, y, h, gate_w, gate_b, sig);

    // 4. out projection with final fused epilogue:
    //    out = x + sig * (y @ out_w^T + out_b)
    dim3 g2(PD / 128, (PM + 127) / 128);
    mma_nt<3><<<g2, 256, GEMM_SMEM>>>(y, out_w, out_b, out, PM, PD, PD,
                                      x, sig, nullptr);
}